// round 16
// baseline (speedup 1.0000x reference)
#include <cuda_runtime.h>
#include <cuda_bf16.h>
#include <cuda_fp16.h>
#include <math.h>
#include <stdint.h>

// ---------------------------------------------------------------------------
// x(8192,512) @ w_qkv(512,1536) -> 64-head attention (n=1024, dh=64,
// scale=8^-0.5) -> @ w_out(512,512) + b_out. fp32 in/out, rel_err < 1e-3.
// Round 16: slice-granular cp.async groups + partial waits. mma on k-slice q
// starts as soon as slice q lands (wait_group 3-q), instead of waiting for
// the full tile. Same buffers/lifetimes as the proven round-15 kernels.
// ---------------------------------------------------------------------------

__device__ alignas(16) __nv_bfloat16 g_xh[8192 * 512], g_xl[8192 * 512];      // [m][k]
__device__ alignas(16) __nv_bfloat16 g_wqh[1536 * 512], g_wql[1536 * 512];    // [n][k]
__device__ alignas(16) __half        g_wof[512 * 512];                        // [n][k] fp16
__device__ alignas(16) __nv_bfloat16 g_Qh[64 * 1024 * 64], g_Ql[64 * 1024 * 64]; // [bh][n][d]
__device__ alignas(16) __nv_bfloat16 g_Kh[64 * 1024 * 64], g_Kl[64 * 1024 * 64]; // [bh][n][d]
__device__ alignas(16) __half        g_Vf[64 * 1024 * 64];                       // [bh][n][d]
__device__ alignas(16) __half        g_Of[8192 * 512];                           // [b*n][h*64+d]

// ---------------------------------------------------------------------------
__device__ __forceinline__ float fast_exp(float x) {
    float y = x * 1.4426950408889634f;
    y = fmaxf(y, -126.0f);
    y = fminf(y, 126.0f);
    float nf = rintf(y);
    float t = (y - nf) * 0.6931471805599453f;
    float p = 8.3333337e-3f;
    p = fmaf(p, t, 4.1666668e-2f);
    p = fmaf(p, t, 0.16666667f);
    p = fmaf(p, t, 0.5f);
    p = fmaf(p, t, 1.0f);
    p = fmaf(p, t, 1.0f);
    return p * __int_as_float(((int)nf + 127) << 23);
}

// ---------------------------------------------------------------------------
__device__ __forceinline__ uint32_t smem_u32(const void* p) {
    return (uint32_t)__cvta_generic_to_shared(p);
}
__device__ __forceinline__ void ldsm4(uint32_t r[4], const void* p) {
    uint32_t a = smem_u32(p);
    asm volatile("ldmatrix.sync.aligned.m8n8.x4.shared.b16 {%0,%1,%2,%3}, [%4];"
                 : "=r"(r[0]), "=r"(r[1]), "=r"(r[2]), "=r"(r[3]) : "r"(a));
}
__device__ __forceinline__ void ldsm4t(uint32_t r[4], const void* p) {
    uint32_t a = smem_u32(p);
    asm volatile("ldmatrix.sync.aligned.m8n8.x4.trans.shared.b16 {%0,%1,%2,%3}, [%4];"
                 : "=r"(r[0]), "=r"(r[1]), "=r"(r[2]), "=r"(r[3]) : "r"(a));
}
__device__ __forceinline__ void mma_bf16(float c[4], const uint32_t a[4],
                                         uint32_t b0, uint32_t b1) {
    asm volatile(
        "mma.sync.aligned.m16n8k16.row.col.f32.bf16.bf16.f32 "
        "{%0,%1,%2,%3}, {%4,%5,%6,%7}, {%8,%9}, {%0,%1,%2,%3};"
        : "+f"(c[0]), "+f"(c[1]), "+f"(c[2]), "+f"(c[3])
        : "r"(a[0]), "r"(a[1]), "r"(a[2]), "r"(a[3]), "r"(b0), "r"(b1));
}
__device__ __forceinline__ void mma_f16(float c[4], const uint32_t a[4],
                                        uint32_t b0, uint32_t b1) {
    asm volatile(
        "mma.sync.aligned.m16n8k16.row.col.f32.f16.f16.f32 "
        "{%0,%1,%2,%3}, {%4,%5,%6,%7}, {%8,%9}, {%0,%1,%2,%3};"
        : "+f"(c[0]), "+f"(c[1]), "+f"(c[2]), "+f"(c[3])
        : "r"(a[0]), "r"(a[1]), "r"(a[2]), "r"(a[3]), "r"(b0), "r"(b1));
}
__device__ __forceinline__ uint32_t pack_half2(float lo, float hi) {
    __half2 h = __floats2half2_rn(lo, hi);
    return *reinterpret_cast<uint32_t*>(&h);
}
__device__ __forceinline__ void cp16(void* s, const void* g) {
    asm volatile("cp.async.cg.shared.global [%0], [%1], 16;" :: "r"(smem_u32(s)), "l"(g));
}
__device__ __forceinline__ void cp_commit() {
    asm volatile("cp.async.commit_group;");
}
template <int N>
__device__ __forceinline__ void cp_wait() {
    asm volatile("cp.async.wait_group %0;" :: "n"(N));
}

// ---------------------------------------------------------------------------
// Prepasses (device symbols touched only from device code)
__global__ __launch_bounds__(256) void prep_x(const float* __restrict__ x) {
    int i = blockIdx.x * 256 + threadIdx.x;
    float4 v = *(const float4*)&x[(size_t)i * 4];
    alignas(8) __nv_bfloat16 hh[4], ll[4];
    float vv[4] = {v.x, v.y, v.z, v.w};
#pragma unroll
    for (int k = 0; k < 4; k++) {
        hh[k] = __float2bfloat16(vv[k]);
        ll[k] = __float2bfloat16(vv[k] - __bfloat162float(hh[k]));
    }
    *(uint2*)&g_xh[(size_t)i * 4] = *(const uint2*)hh;
    *(uint2*)&g_xl[(size_t)i * 4] = *(const uint2*)ll;
}

__global__ __launch_bounds__(256) void prep_wq(const float* __restrict__ W) {
    __shared__ float tile[32][33];
    const int c0 = blockIdx.x * 32, r0 = blockIdx.y * 32;
    const int tx = threadIdx.x & 31, ty = threadIdx.x >> 5;
#pragma unroll
    for (int i = ty; i < 32; i += 8)
        tile[i][tx] = W[(size_t)(r0 + i) * 1536 + c0 + tx];
    __syncthreads();
#pragma unroll
    for (int i = ty; i < 32; i += 8) {
        float v = tile[tx][i];
        __nv_bfloat16 h = __float2bfloat16(v);
        size_t o = (size_t)(c0 + i) * 512 + r0 + tx;
        g_wqh[o] = h;
        g_wql[o] = __float2bfloat16(v - __bfloat162float(h));
    }
}

__global__ __launch_bounds__(256) void prep_wo(const float* __restrict__ W) {
    __shared__ float tile[32][33];
    const int c0 = blockIdx.x * 32, r0 = blockIdx.y * 32;
    const int tx = threadIdx.x & 31, ty = threadIdx.x >> 5;
#pragma unroll
    for (int i = ty; i < 32; i += 8)
        tile[i][tx] = W[(size_t)(r0 + i) * 512 + c0 + tx];
    __syncthreads();
#pragma unroll
    for (int i = ty; i < 32; i += 8)
        g_wof[(size_t)(c0 + i) * 512 + r0 + tx] = __float2half_rn(tile[tx][i]);
}

// ---------------------------------------------------------------------------
// Kernel 1: QKV projection. bf16x3, chunk 64, single stage, 2 CTAs/SM.
// NEW: each chunk loads as 4 k-slice groups; kt waits only its slice.
__global__ __launch_bounds__(256, 2) void qkv_gemm_mma() {
    extern __shared__ char sm[];
    __nv_bfloat16* sAh = (__nv_bfloat16*)sm;
    __nv_bfloat16* sAl = sAh + 128 * 72;
    __nv_bfloat16* sBh = sAl + 128 * 72;
    __nv_bfloat16* sBl = sBh + 128 * 72;
    float c[4][4][4];
#pragma unroll
    for (int a = 0; a < 4; a++)
#pragma unroll
        for (int b = 0; b < 4; b++)
#pragma unroll
            for (int d = 0; d < 4; d++) c[a][b][d] = 0.0f;

    const int tid = threadIdx.x, lane = tid & 31, warp = tid >> 5;
    const int wy = warp >> 2, wx = warp & 3;
    const int lr = lane & 15, lc = (lane >> 4) * 8;
    const int row0 = blockIdx.y * 128, col0 = blockIdx.x * 128;
    const __nv_bfloat16 *Ah = g_xh, *Al = g_xl, *Bh = g_wqh, *Bl = g_wql;

    // one k-slice (16 cols) of all 4 matrices; 4 cp16/thread = 16KB; 1 group
#define QLOADQ(kc, q)                                                             \
    {                                                                             \
        int r = tid >> 1, c8 = (tid & 1) * 8 + (q) * 16;                          \
        cp16(&sAh[r * 72 + c8], &Ah[(size_t)(row0 + r) * 512 + (kc) + c8]);       \
        cp16(&sAl[r * 72 + c8], &Al[(size_t)(row0 + r) * 512 + (kc) + c8]);       \
        cp16(&sBh[r * 72 + c8], &Bh[(size_t)(col0 + r) * 512 + (kc) + c8]);       \
        cp16(&sBl[r * 72 + c8], &Bl[(size_t)(col0 + r) * 512 + (kc) + c8]);       \
        cp_commit();                                                              \
    }

    for (int kc = 0; kc < 512; kc += 64) {
        QLOADQ(kc, 0)
        QLOADQ(kc, 1)
        QLOADQ(kc, 2)
        QLOADQ(kc, 3)
#pragma unroll
        for (int kt = 0; kt < 4; kt++) {
            if (kt == 0) cp_wait<3>();
            else if (kt == 1) cp_wait<2>();
            else if (kt == 2) cp_wait<1>();
            else cp_wait<0>();
            __syncthreads();
            uint32_t ah[4][4], al[4][4];
#pragma unroll
            for (int mt = 0; mt < 4; mt++) {
                int ro = (wy * 64 + mt * 16 + lr) * 72 + kt * 16 + lc;
                ldsm4(ah[mt], &sAh[ro]);
                ldsm4(al[mt], &sAl[ro]);
            }
#pragma unroll
            for (int nt16 = 0; nt16 < 2; nt16++) {
                uint32_t bh[4], bl[4];
                int ro = (wx * 32 + nt16 * 16 + lr) * 72 + kt * 16 + lc;
                ldsm4(bh, &sBh[ro]);
                ldsm4(bl, &sBl[ro]);
#pragma unroll
                for (int mt = 0; mt < 4; mt++) {
                    float* c0 = c[mt][nt16 * 2];
                    float* c1 = c[mt][nt16 * 2 + 1];
                    mma_bf16(c0, ah[mt], bh[0], bh[2]);
                    mma_bf16(c1, ah[mt], bh[1], bh[3]);
                    mma_bf16(c0, ah[mt], bl[0], bl[2]);
                    mma_bf16(c1, ah[mt], bl[1], bl[3]);
                    mma_bf16(c0, al[mt], bh[0], bh[2]);
                    mma_bf16(c1, al[mt], bh[1], bh[3]);
                }
            }
        }
        __syncthreads();   // all reads of this chunk done before refill
    }
#undef QLOADQ

    // Epilogue (round-11 proven): stage to Cs, scatter Q/K hi/lo + V fp16
    float* Cs = (float*)sm;
    __syncthreads();
    const int g = lane >> 2, tig = lane & 3;
#pragma unroll
    for (int mt = 0; mt < 4; mt++)
#pragma unroll
        for (int nt = 0; nt < 4; nt++) {
            int r = wy * 64 + mt * 16 + g, cc = wx * 32 + nt * 8 + tig * 2;
            Cs[r * 132 + cc] = c[mt][nt][0];
            Cs[r * 132 + cc + 1] = c[mt][nt][1];
            Cs[(r + 8) * 132 + cc] = c[mt][nt][2];
            Cs[(r + 8) * 132 + cc + 1] = c[mt][nt][3];
        }
    __syncthreads();

    const int ty = tid >> 4, tx = tid & 15;
    const int jloc = tx * 8, j0 = col0 + jloc;
    const int h = j0 / 192, part = (j0 % 192) >> 6, d0 = j0 & 63;
    const int rowg0 = row0 + ty * 8;
    const int b_idx = rowg0 >> 10, n0 = rowg0 & 1023, bh = b_idx * 8 + h;
    const float qs = 0.35355339059327373f;   // 8^-0.5 (batch-size scale!)

#pragma unroll
    for (int r = 0; r < 8; r++) {
        float v[8];
#pragma unroll
        for (int k = 0; k < 8; k++) v[k] = Cs[(ty * 8 + r) * 132 + jloc + k];
        size_t base = ((size_t)bh * 1024 + n0 + r) * 64 + d0;
        if (part == 0) {
            alignas(16) __nv_bfloat16 hh[8], ll[8];
#pragma unroll
            for (int k = 0; k < 8; k++) {
                float sv = v[k] * qs;
                hh[k] = __float2bfloat16(sv);
                ll[k] = __float2bfloat16(sv - __bfloat162float(hh[k]));
            }
            *(uint4*)&g_Qh[base] = *(const uint4*)hh;
            *(uint4*)&g_Ql[base] = *(const uint4*)ll;
        } else if (part == 1) {
            alignas(16) __nv_bfloat16 hh[8], ll[8];
#pragma unroll
            for (int k = 0; k < 8; k++) {
                hh[k] = __float2bfloat16(v[k]);
                ll[k] = __float2bfloat16(v[k] - __bfloat162float(hh[k]));
            }
            *(uint4*)&g_Kh[base] = *(const uint4*)hh;
            *(uint4*)&g_Kl[base] = *(const uint4*)ll;
        } else {
            alignas(16) __half hv[8];
#pragma unroll
            for (int k = 0; k < 8; k++) hv[k] = __float2half_rn(v[k]);
            *(uint4*)&g_Vf[base] = *(const uint4*)hv;
        }
    }
}

// ---------------------------------------------------------------------------
// Kernel 2: fused flash attention. V double-buffered (proven round 15).
// NEW: K loads split into 4 k-slice groups + V group; S-phase waits per-slice
// (wait_group 4/3/2/1), V waited (0) only before PV.
__global__ __launch_bounds__(256, 2) void attn_mma() {
    extern __shared__ char sm[];
    __nv_bfloat16* sQh = (__nv_bfloat16*)sm;
    __nv_bfloat16* sQl = sQh + 128 * 72;
    __nv_bfloat16* sKh = sQl + 128 * 72;
    __nv_bfloat16* sKl = sKh + 128 * 72;
    __half* sV0 = (__half*)(sKl + 128 * 72);
    __half* sV1 = sV0 + 128 * 72;

    const int tid = threadIdx.x, lane = tid & 31, warp = tid >> 5;
    const int g = lane >> 2, tig = lane & 3;
    const int lr = lane & 15, lc = (lane >> 4) * 8;
    const int vrow = ((lane >> 3) & 1) * 8 + (lane & 7);
    const int vcol = (lane >> 4) * 8;

    const int bh = blockIdx.y;
    const int i0 = blockIdx.x * 128;
    const size_t hb = (size_t)bh * 1024 * 64;

    // one 16-col k-slice of K hi+lo: 2 cp16/thread; caller commits
#define LOAD_K_SLICE(j0, q)                                                       \
    {                                                                             \
        int r = tid >> 1, c8 = (tid & 1) * 8 + (q) * 16;                          \
        cp16(&sKh[r * 72 + c8], &g_Kh[hb + (size_t)((j0) + r) * 64 + c8]);        \
        cp16(&sKl[r * 72 + c8], &g_Kl[hb + (size_t)((j0) + r) * 64 + c8]);        \
        cp_commit();                                                              \
    }
#define LOAD_V(j0, dst)                                                           \
    {                                                                             \
        _Pragma("unroll") for (int i = 0; i < 4; i++) {                           \
            int idx = i * 256 + tid;                                              \
            int r = idx >> 3, c8 = (idx & 7) * 8;                                 \
            cp16(&(dst)[r * 72 + c8], &g_Vf[hb + (size_t)((j0) + r) * 64 + c8]);  \
        }                                                                         \
        cp_commit();                                                              \
    }

    // prologue: [Q + K-slice0], K-slice1..3, V(0)  -> 5 groups
#pragma unroll
    for (int i = 0; i < 4; i++) {
        int idx = i * 256 + tid;
        int r = idx >> 3, c8 = (idx & 7) * 8;
        cp16(&sQh[r * 72 + c8], &g_Qh[hb + (size_t)(i0 + r) * 64 + c8]);
        cp16(&sQl[r * 72 + c8], &g_Ql[hb + (size_t)(i0 + r) * 64 + c8]);
    }
    LOAD_K_SLICE(0, 0)     // commits group 0 (with Q)
    LOAD_K_SLICE(0, 1)
    LOAD_K_SLICE(0, 2)
    LOAD_K_SLICE(0, 3)
    LOAD_V(0, sV0)

    float o[8][4];
#pragma unroll
    for (int d = 0; d < 8; d++)
#pragma unroll
        for (int k = 0; k < 4; k++) o[d][k] = 0.0f;
    float m0 = -1e30f, m1 = -1e30f, l0 = 0.0f, l1 = 0.0f;

    for (int jt = 0; jt < 8; jt++) {
        // ---- S = Q K^T, waiting per k-slice ----
        float s[16][4];
#pragma unroll
        for (int t = 0; t < 16; t++)
#pragma unroll
            for (int k = 0; k < 4; k++) s[t][k] = 0.0f;

#pragma unroll
        for (int kt = 0; kt < 4; kt++) {
            if (kt == 0) cp_wait<4>();
            else if (kt == 1) cp_wait<3>();
            else if (kt == 2) cp_wait<2>();
            else cp_wait<1>();
            __syncthreads();
            uint32_t qh[4], ql[4];
            int qo = (warp * 16 + lr) * 72 + kt * 16 + lc;
            ldsm4(qh, &sQh[qo]);
            ldsm4(ql, &sQl[qo]);
#pragma unroll
            for (int nt = 0; nt < 8; nt++) {
                uint32_t kh[4], kl[4];
                int ko = (nt * 16 + lr) * 72 + kt * 16 + lc;
                ldsm4(kh, &sKh[ko]);
                ldsm4(kl, &sKl[ko]);
                float* s0 = s[nt * 2];
                float* s1 = s[nt * 2 + 1];
                mma_bf16(s0, qh, kh[0], kh[2]);
                mma_bf16(s1, qh, kh[1], kh[3]);
                mma_bf16(s0, qh, kl[0], kl[2]);
                mma_bf16(s1, qh, kl[1], kl[3]);
                mma_bf16(s0, ql, kh[0], kh[2]);
                mma_bf16(s1, ql, kh[1], kh[3]);
            }
        }

        // ---- online softmax ----
        float rmax0 = -1e30f, rmax1 = -1e30f;
#pragma unroll
        for (int t = 0; t < 16; t++) {
            rmax0 = fmaxf(rmax0, fmaxf(s[t][0], s[t][1]));
            rmax1 = fmaxf(rmax1, fmaxf(s[t][2], s[t][3]));
        }
        rmax0 = fmaxf(rmax0, __shfl_xor_sync(0xffffffffu, rmax0, 1));
        rmax0 = fmaxf(rmax0, __shfl_xor_sync(0xffffffffu, rmax0, 2));
        rmax1 = fmaxf(rmax1, __shfl_xor_sync(0xffffffffu, rmax1, 1));
        rmax1 = fmaxf(rmax1, __shfl_xor_sync(0xffffffffu, rmax1, 2));
        float mn0 = fmaxf(m0, rmax0), mn1 = fmaxf(m1, rmax1);
        float cr0 = fast_exp(m0 - mn0), cr1 = fast_exp(m1 - mn1);
        float sum0 = 0.0f, sum1 = 0.0f;
#pragma unroll
        for (int t = 0; t < 16; t++) {
            s[t][0] = fast_exp(s[t][0] - mn0);
            s[t][1] = fast_exp(s[t][1] - mn0);
            s[t][2] = fast_exp(s[t][2] - mn1);
            s[t][3] = fast_exp(s[t][3] - mn1);
            sum0 += s[t][0] + s[t][1];
            sum1 += s[t][2] + s[t][3];
        }
        sum0 += __shfl_xor_sync(0xffffffffu, sum0, 1);
        sum0 += __shfl_xor_sync(0xffffffffu, sum0, 2);
        sum1 += __shfl_xor_sync(0xffffffffu, sum1, 1);
        sum1 += __shfl_xor_sync(0xffffffffu, sum1, 2);
        l0 = l0 * cr0 + sum0;
        l1 = l1 * cr1 + sum1;
        m0 = mn0;
        m1 = mn1;
#pragma unroll
        for (int d = 0; d < 8; d++) {
            o[d][0] *= cr0; o[d][1] *= cr0;
            o[d][2] *= cr1; o[d][3] *= cr1;
        }

        // ---- V(jt) ready; all S reads done after sync; refill for jt+1 ----
        cp_wait<0>();
        __syncthreads();
        if (jt < 7) {
            const int jn = (jt + 1) * 128;
            LOAD_K_SLICE(jn, 0)
            LOAD_K_SLICE(jn, 1)
            LOAD_K_SLICE(jn, 2)
            LOAD_K_SLICE(jn, 3)
            LOAD_V(jn, ((jt + 1) & 1) ? sV1 : sV0)
        }

        // ---- O += P V (current V buffer; refills target K + other V) ----
        __half* sV = (jt & 1) ? sV1 : sV0;
#pragma unroll
        for (int jt16 = 0; jt16 < 8; jt16++) {
            uint32_t a[4];
            a[0] = pack_half2(s[jt16 * 2][0], s[jt16 * 2][1]);
            a[1] = pack_half2(s[jt16 * 2][2], s[jt16 * 2][3]);
            a[2] = pack_half2(s[jt16 * 2 + 1][0], s[jt16 * 2 + 1][1]);
            a[3] = pack_half2(s[jt16 * 2 + 1][2], s[jt16 * 2 + 1][3]);
#pragma unroll
            for (int dt16 = 0; dt16 < 4; dt16++) {
                uint32_t v[4];
                ldsm4t(v, &sV[(jt16 * 16 + vrow) * 72 + dt16 * 16 + vcol]);
                mma_f16(o[dt16 * 2], a, v[0], v[1]);
                mma_f16(o[dt16 * 2 + 1], a, v[2], v[3]);
            }
        }
    }
#undef LOAD_K_SLICE
#undef LOAD_V

    // Epilogue: normalize, write fp16 g_Of [b*n][h*64+d]
    const float inv0 = 1.0f / l0, inv1 = 1.0f / l1;
    const int b_idx = bh >> 3, h = bh & 7;
    const size_t rowa = (size_t)b_idx * 1024 + i0 + warp * 16 + g;
    const size_t rowb = rowa + 8;
    const int colb = h * 64 + tig * 2;
#pragma unroll
    for (int dt = 0; dt < 8; dt++) {
        int col = colb + dt * 8;
        *(__half2*)&g_Of[rowa * 512 + col] =
            __floats2half2_rn(o[dt][0] * inv0, o[dt][1] * inv0);
        *(__half2*)&g_Of[rowb * 512 + col] =
            __floats2half2_rn(o[dt][2] * inv1, o[dt][3] * inv1);
    }
}

// ---------------------------------------------------------------------------
// Kernel 3: out = O @ w_out + b_out — round-11/15 proven fp16 2-stage verbatim.
__global__ __launch_bounds__(256, 2) void out_f16(const float* __restrict__ bias,
                                                  float* __restrict__ out) {
    extern __shared__ char sm[];
    const int STAGE = 2 * 128 * 72 * 2;   // 36864
    float c[4][4][4];
#pragma unroll
    for (int a = 0; a < 4; a++)
#pragma unroll
        for (int b = 0; b < 4; b++)
#pragma unroll
            for (int d = 0; d < 4; d++) c[a][b][d] = 0.0f;

    const int tid = threadIdx.x, lane = tid & 31, warp = tid >> 5;
    const int wy = warp >> 2, wx = warp & 3;
    const int lr = lane & 15, lc = (lane >> 4) * 8;
    const int row0 = blockIdx.y * 128, col0 = blockIdx.x * 128;

#define LOADF(kc, st)                                                             \
    {                                                                             \
        __half* dA = (__half*)(sm + (st) * STAGE);                                \
        __half* dB = dA + 128 * 72;                                               \
        _Pragma("unroll") for (int i = 0; i < 4; i++) {                           \
            int idx = i * 256 + tid;                                              \
            int r = idx >> 3, c8 = (idx & 7) * 8;                                 \
            cp16(&dA[r * 72 + c8], &g_Of[(size_t)(row0 + r) * 512 + (kc) + c8]);  \
            cp16(&dB[r * 72 + c8], &g_wof[(size_t)(col0 + r) * 512 + (kc) + c8]); \
        }                                                                         \
        cp_commit();                                                              \
    }

    LOADF(0, 0)
    for (int ks = 0; ks < 8; ks++) {
        if (ks < 7) {
            LOADF((ks + 1) * 64, (ks + 1) & 1)
            cp_wait<1>();
        } else {
            cp_wait<0>();
        }
        __syncthreads();
        __half* sA = (__half*)(sm + (ks & 1) * STAGE);
        __half* sB = sA + 128 * 72;
#pragma unroll
        for (int kt = 0; kt < 4; kt++) {
            uint32_t af[4][4];
#pragma unroll
            for (int mt = 0; mt < 4; mt++)
                ldsm4(af[mt], &sA[(wy * 64 + mt * 16 + lr) * 72 + kt * 16 + lc]);
#pragma unroll
            for (int nt16 = 0; nt16 < 2; nt16++) {
                uint32_t bf[4];
                ldsm4(bf, &sB[(wx * 32 + nt16 * 16 + lr) * 72 + kt * 16 + lc]);
#pragma unroll
                for (int mt = 0; mt < 4; mt++) {
                    mma_f16(c[mt][nt16 * 2], af[mt], bf[0], bf[2]);
                    mma_f16(c[mt][nt16 * 2 + 1], af[mt], bf[1], bf[3]);
                }
            }
        }
        __syncthreads();
    }
#undef LOADF

    const int g = lane >> 2, tig = lane & 3;
#pragma unroll
    for (int mt = 0; mt < 4; mt++)
#pragma unroll
        for (int nt = 0; nt < 4; nt++) {
            int r = row0 + wy * 64 + mt * 16 + g;
            int cc = col0 + wx * 32 + nt * 8 + tig * 2;
            float b0 = bias[cc], b1 = bias[cc + 1];
            *(float2*)&out[(size_t)r * 512 + cc] =
                make_float2(c[mt][nt][0] + b0, c[mt][nt][1] + b1);
            *(float2*)&out[(size_t)(r + 8) * 512 + cc] =
                make_float2(c[mt][nt][2] + b0, c[mt][nt][3] + b1);
        }
}

// ---------------------------------------------------------------------------
extern "C" void kernel_launch(void* const* d_in, const int* in_sizes, int n_in,
                              void* d_out, int out_size) {
    const float* x     = (const float*)d_in[0];
    const float* w_qkv = (const float*)d_in[1];
    const float* w_out = (const float*)d_in[2];
    const float* b_out = (const float*)d_in[3];
    float* out = (float*)d_out;

    const int gemm_smem = 4 * 128 * 72 * 2;     // 73728 B (covers Cs 67584)
    const int attn_smem = 6 * 128 * 72 * 2;     // 110592 B
    const int outf_smem = 2 * 2 * 128 * 72 * 2; // 73728 B
    cudaFuncSetAttribute(qkv_gemm_mma, cudaFuncAttributeMaxDynamicSharedMemorySize, gemm_smem);
    cudaFuncSetAttribute(attn_mma, cudaFuncAttributeMaxDynamicSharedMemorySize, attn_smem);
    cudaFuncSetAttribute(out_f16, cudaFuncAttributeMaxDynamicSharedMemorySize, outf_smem);

    prep_x<<<4096, 256>>>(x);
    prep_wq<<<dim3(48, 16), 256>>>(w_qkv);
    prep_wo<<<dim3(16, 16), 256>>>(w_out);
    qkv_gemm_mma<<<dim3(12, 64), 256, gemm_smem>>>();
    attn_mma<<<dim3(8, 64), 256, attn_smem>>>();
    out_f16<<<dim3(4, 64), 256, outf_smem>>>(b_out, out);
}

// round 17
// speedup vs baseline: 1.3062x; 1.3062x over previous
#include <cuda_runtime.h>
#include <cuda_bf16.h>
#include <cuda_fp16.h>
#include <math.h>
#include <stdint.h>

// ---------------------------------------------------------------------------
// x(8192,512) @ w_qkv(512,1536) -> 64-head attention (n=1024, dh=64,
// scale=8^-0.5) -> @ w_out(512,512) + b_out. fp32 in/out, rel_err < 1e-3.
// Round 17: R15 GEMMs (proven). Attention: softmax exp moved to MUFU via
// ex2.approx.f16x2 (result doubles as the packed PV A-operand), and K/V in
// separate cp.async groups so V(jt+1) loads span the whole S-phase.
// ---------------------------------------------------------------------------

__device__ alignas(16) __nv_bfloat16 g_xh[8192 * 512], g_xl[8192 * 512];      // [m][k]
__device__ alignas(16) __nv_bfloat16 g_wqh[1536 * 512], g_wql[1536 * 512];    // [n][k]
__device__ alignas(16) __half        g_wof[512 * 512];                        // [n][k] fp16
__device__ alignas(16) __nv_bfloat16 g_Qh[64 * 1024 * 64], g_Ql[64 * 1024 * 64]; // [bh][n][d]
__device__ alignas(16) __nv_bfloat16 g_Kh[64 * 1024 * 64], g_Kl[64 * 1024 * 64]; // [bh][n][d]
__device__ alignas(16) __half        g_Vf[64 * 1024 * 64];                       // [bh][n][d]
__device__ alignas(16) __half        g_Of[8192 * 512];                           // [b*n][h*64+d]

// ---------------------------------------------------------------------------
__device__ __forceinline__ float fast_exp(float x) {
    float y = x * 1.4426950408889634f;
    y = fmaxf(y, -126.0f);
    y = fminf(y, 126.0f);
    float nf = rintf(y);
    float t = (y - nf) * 0.6931471805599453f;
    float p = 8.3333337e-3f;
    p = fmaf(p, t, 4.1666668e-2f);
    p = fmaf(p, t, 0.16666667f);
    p = fmaf(p, t, 0.5f);
    p = fmaf(p, t, 1.0f);
    p = fmaf(p, t, 1.0f);
    return p * __int_as_float(((int)nf + 127) << 23);
}

// ---------------------------------------------------------------------------
__device__ __forceinline__ uint32_t smem_u32(const void* p) {
    return (uint32_t)__cvta_generic_to_shared(p);
}
__device__ __forceinline__ void ldsm4(uint32_t r[4], const void* p) {
    uint32_t a = smem_u32(p);
    asm volatile("ldmatrix.sync.aligned.m8n8.x4.shared.b16 {%0,%1,%2,%3}, [%4];"
                 : "=r"(r[0]), "=r"(r[1]), "=r"(r[2]), "=r"(r[3]) : "r"(a));
}
__device__ __forceinline__ void ldsm4t(uint32_t r[4], const void* p) {
    uint32_t a = smem_u32(p);
    asm volatile("ldmatrix.sync.aligned.m8n8.x4.trans.shared.b16 {%0,%1,%2,%3}, [%4];"
                 : "=r"(r[0]), "=r"(r[1]), "=r"(r[2]), "=r"(r[3]) : "r"(a));
}
__device__ __forceinline__ void mma_bf16(float c[4], const uint32_t a[4],
                                         uint32_t b0, uint32_t b1) {
    asm volatile(
        "mma.sync.aligned.m16n8k16.row.col.f32.bf16.bf16.f32 "
        "{%0,%1,%2,%3}, {%4,%5,%6,%7}, {%8,%9}, {%0,%1,%2,%3};"
        : "+f"(c[0]), "+f"(c[1]), "+f"(c[2]), "+f"(c[3])
        : "r"(a[0]), "r"(a[1]), "r"(a[2]), "r"(a[3]), "r"(b0), "r"(b1));
}
__device__ __forceinline__ void mma_f16(float c[4], const uint32_t a[4],
                                        uint32_t b0, uint32_t b1) {
    asm volatile(
        "mma.sync.aligned.m16n8k16.row.col.f32.f16.f16.f32 "
        "{%0,%1,%2,%3}, {%4,%5,%6,%7}, {%8,%9}, {%0,%1,%2,%3};"
        : "+f"(c[0]), "+f"(c[1]), "+f"(c[2]), "+f"(c[3])
        : "r"(a[0]), "r"(a[1]), "r"(a[2]), "r"(a[3]), "r"(b0), "r"(b1));
}
__device__ __forceinline__ void cp16(void* s, const void* g) {
    asm volatile("cp.async.cg.shared.global [%0], [%1], 16;" :: "r"(smem_u32(s)), "l"(g));
}
__device__ __forceinline__ void cp_commit() {
    asm volatile("cp.async.commit_group;");
}
template <int N>
__device__ __forceinline__ void cp_wait() {
    asm volatile("cp.async.wait_group %0;" :: "n"(N));
}

// ---------------------------------------------------------------------------
// Prepasses (device symbols touched only from device code)
__global__ __launch_bounds__(256) void prep_x(const float* __restrict__ x) {
    int i = blockIdx.x * 256 + threadIdx.x;
    float4 v = *(const float4*)&x[(size_t)i * 4];
    alignas(8) __nv_bfloat16 hh[4], ll[4];
    float vv[4] = {v.x, v.y, v.z, v.w};
#pragma unroll
    for (int k = 0; k < 4; k++) {
        hh[k] = __float2bfloat16(vv[k]);
        ll[k] = __float2bfloat16(vv[k] - __bfloat162float(hh[k]));
    }
    *(uint2*)&g_xh[(size_t)i * 4] = *(const uint2*)hh;
    *(uint2*)&g_xl[(size_t)i * 4] = *(const uint2*)ll;
}

__global__ __launch_bounds__(256) void prep_wq(const float* __restrict__ W) {
    __shared__ float tile[32][33];
    const int c0 = blockIdx.x * 32, r0 = blockIdx.y * 32;
    const int tx = threadIdx.x & 31, ty = threadIdx.x >> 5;
#pragma unroll
    for (int i = ty; i < 32; i += 8)
        tile[i][tx] = W[(size_t)(r0 + i) * 1536 + c0 + tx];
    __syncthreads();
#pragma unroll
    for (int i = ty; i < 32; i += 8) {
        float v = tile[tx][i];
        __nv_bfloat16 h = __float2bfloat16(v);
        size_t o = (size_t)(c0 + i) * 512 + r0 + tx;
        g_wqh[o] = h;
        g_wql[o] = __float2bfloat16(v - __bfloat162float(h));
    }
}

__global__ __launch_bounds__(256) void prep_wo(const float* __restrict__ W) {
    __shared__ float tile[32][33];
    const int c0 = blockIdx.x * 32, r0 = blockIdx.y * 32;
    const int tx = threadIdx.x & 31, ty = threadIdx.x >> 5;
#pragma unroll
    for (int i = ty; i < 32; i += 8)
        tile[i][tx] = W[(size_t)(r0 + i) * 512 + c0 + tx];
    __syncthreads();
#pragma unroll
    for (int i = ty; i < 32; i += 8)
        g_wof[(size_t)(c0 + i) * 512 + r0 + tx] = __float2half_rn(tile[tx][i]);
}

// ---------------------------------------------------------------------------
// bf16x3 mainloop (round-11/15 proven): 128x128, K=512, chunk 64, single
// stage, 2 CTAs/SM. Smem: 4 x [128][72] bf16 = 73728 B.
__device__ __forceinline__ void gemm_loop_bf16(
    const __nv_bfloat16* __restrict__ Ah, const __nv_bfloat16* __restrict__ Al,
    const __nv_bfloat16* __restrict__ Bh, const __nv_bfloat16* __restrict__ Bl,
    int row0, int col0, char* sm, float c[4][4][4]) {
    __nv_bfloat16* sAh = (__nv_bfloat16*)sm;
    __nv_bfloat16* sAl = sAh + 128 * 72;
    __nv_bfloat16* sBh = sAl + 128 * 72;
    __nv_bfloat16* sBl = sBh + 128 * 72;
    const int tid = threadIdx.x, lane = tid & 31, warp = tid >> 5;
    const int wy = warp >> 2, wx = warp & 3;
    const int lr = lane & 15, lc = (lane >> 4) * 8;

    for (int kc = 0; kc < 512; kc += 64) {
#pragma unroll
        for (int i = 0; i < 4; i++) {
            int idx = i * 256 + tid;
            int r = idx >> 3, c8 = (idx & 7) * 8;
            cp16(&sAh[r * 72 + c8], &Ah[(size_t)(row0 + r) * 512 + kc + c8]);
            cp16(&sAl[r * 72 + c8], &Al[(size_t)(row0 + r) * 512 + kc + c8]);
            cp16(&sBh[r * 72 + c8], &Bh[(size_t)(col0 + r) * 512 + kc + c8]);
            cp16(&sBl[r * 72 + c8], &Bl[(size_t)(col0 + r) * 512 + kc + c8]);
        }
        cp_commit();
        cp_wait<0>();
        __syncthreads();
#pragma unroll
        for (int kt = 0; kt < 4; kt++) {
            uint32_t ah[4][4], al[4][4];
#pragma unroll
            for (int mt = 0; mt < 4; mt++) {
                int ro = (wy * 64 + mt * 16 + lr) * 72 + kt * 16 + lc;
                ldsm4(ah[mt], &sAh[ro]);
                ldsm4(al[mt], &sAl[ro]);
            }
#pragma unroll
            for (int nt16 = 0; nt16 < 2; nt16++) {
                uint32_t bh[4], bl[4];
                int ro = (wx * 32 + nt16 * 16 + lr) * 72 + kt * 16 + lc;
                ldsm4(bh, &sBh[ro]);
                ldsm4(bl, &sBl[ro]);
#pragma unroll
                for (int mt = 0; mt < 4; mt++) {
                    float* c0 = c[mt][nt16 * 2];
                    float* c1 = c[mt][nt16 * 2 + 1];
                    mma_bf16(c0, ah[mt], bh[0], bh[2]);
                    mma_bf16(c1, ah[mt], bh[1], bh[3]);
                    mma_bf16(c0, ah[mt], bl[0], bl[2]);
                    mma_bf16(c1, ah[mt], bl[1], bl[3]);
                    mma_bf16(c0, al[mt], bh[0], bh[2]);
                    mma_bf16(c1, al[mt], bh[1], bh[3]);
                }
            }
        }
        __syncthreads();   // protect buffer before next chunk's cp.async
    }
}

// ---------------------------------------------------------------------------
// Kernel 1: QKV projection (round-11/15 proven verbatim)
__global__ __launch_bounds__(256, 2) void qkv_gemm_mma() {
    extern __shared__ char sm[];
    float c[4][4][4];
#pragma unroll
    for (int a = 0; a < 4; a++)
#pragma unroll
        for (int b = 0; b < 4; b++)
#pragma unroll
            for (int d = 0; d < 4; d++) c[a][b][d] = 0.0f;

    const int row0 = blockIdx.y * 128, col0 = blockIdx.x * 128;
    gemm_loop_bf16(g_xh, g_xl, g_wqh, g_wql, row0, col0, sm, c);

    float* Cs = (float*)sm;
    __syncthreads();
    const int lane = threadIdx.x & 31, warp = threadIdx.x >> 5;
    const int wy = warp >> 2, wx = warp & 3, g = lane >> 2, tig = lane & 3;
#pragma unroll
    for (int mt = 0; mt < 4; mt++)
#pragma unroll
        for (int nt = 0; nt < 4; nt++) {
            int r = wy * 64 + mt * 16 + g, cc = wx * 32 + nt * 8 + tig * 2;
            Cs[r * 132 + cc] = c[mt][nt][0];
            Cs[r * 132 + cc + 1] = c[mt][nt][1];
            Cs[(r + 8) * 132 + cc] = c[mt][nt][2];
            Cs[(r + 8) * 132 + cc + 1] = c[mt][nt][3];
        }
    __syncthreads();

    const int tid = threadIdx.x;
    const int ty = tid >> 4, tx = tid & 15;
    const int jloc = tx * 8, j0 = col0 + jloc;
    const int h = j0 / 192, part = (j0 % 192) >> 6, d0 = j0 & 63;
    const int rowg0 = row0 + ty * 8;
    const int b_idx = rowg0 >> 10, n0 = rowg0 & 1023, bh = b_idx * 8 + h;
    const float qs = 0.35355339059327373f;   // 8^-0.5 (batch-size scale!)

#pragma unroll
    for (int r = 0; r < 8; r++) {
        float v[8];
#pragma unroll
        for (int k = 0; k < 8; k++) v[k] = Cs[(ty * 8 + r) * 132 + jloc + k];
        size_t base = ((size_t)bh * 1024 + n0 + r) * 64 + d0;
        if (part == 0) {
            alignas(16) __nv_bfloat16 hh[8], ll[8];
#pragma unroll
            for (int k = 0; k < 8; k++) {
                float sv = v[k] * qs;
                hh[k] = __float2bfloat16(sv);
                ll[k] = __float2bfloat16(sv - __bfloat162float(hh[k]));
            }
            *(uint4*)&g_Qh[base] = *(const uint4*)hh;
            *(uint4*)&g_Ql[base] = *(const uint4*)ll;
        } else if (part == 1) {
            alignas(16) __nv_bfloat16 hh[8], ll[8];
#pragma unroll
            for (int k = 0; k < 8; k++) {
                hh[k] = __float2bfloat16(v[k]);
                ll[k] = __float2bfloat16(v[k] - __bfloat162float(hh[k]));
            }
            *(uint4*)&g_Kh[base] = *(const uint4*)hh;
            *(uint4*)&g_Kl[base] = *(const uint4*)ll;
        } else {
            alignas(16) __half hv[8];
#pragma unroll
            for (int k = 0; k < 8; k++) hv[k] = __float2half_rn(v[k]);
            *(uint4*)&g_Vf[base] = *(const uint4*)hv;
        }
    }
}

// ---------------------------------------------------------------------------
// Kernel 2: fused flash attention. V double-buffered; K and V in SEPARATE
// cp.async groups (V rides through the S-phase). Softmax exp on MUFU via
// ex2.approx.f16x2; results double as packed fp16 PV A-operands.
__global__ __launch_bounds__(256, 2) void attn_mma() {
    extern __shared__ char sm[];
    __nv_bfloat16* sQh = (__nv_bfloat16*)sm;
    __nv_bfloat16* sQl = sQh + 128 * 72;
    __nv_bfloat16* sKh = sQl + 128 * 72;
    __nv_bfloat16* sKl = sKh + 128 * 72;
    __half* sV0 = (__half*)(sKl + 128 * 72);
    __half* sV1 = sV0 + 128 * 72;

    const int tid = threadIdx.x, lane = tid & 31, warp = tid >> 5;
    const int g = lane >> 2, tig = lane & 3;
    const int lr = lane & 15, lc = (lane >> 4) * 8;
    const int vrow = ((lane >> 3) & 1) * 8 + (lane & 7);
    const int vcol = (lane >> 4) * 8;
    const float LOG2E = 1.4426950408889634f;

    const int bh = blockIdx.y;
    const int i0 = blockIdx.x * 128;
    const size_t hb = (size_t)bh * 1024 * 64;

#define LOAD_K(j0)                                                                \
    {                                                                             \
        _Pragma("unroll") for (int i = 0; i < 4; i++) {                           \
            int idx = i * 256 + tid;                                              \
            int r = idx >> 3, c8 = (idx & 7) * 8;                                 \
            cp16(&sKh[r * 72 + c8], &g_Kh[hb + (size_t)((j0) + r) * 64 + c8]);    \
            cp16(&sKl[r * 72 + c8], &g_Kl[hb + (size_t)((j0) + r) * 64 + c8]);    \
        }                                                                         \
        cp_commit();                                                              \
    }
#define LOAD_V(j0, dst)                                                           \
    {                                                                             \
        _Pragma("unroll") for (int i = 0; i < 4; i++) {                           \
            int idx = i * 256 + tid;                                              \
            int r = idx >> 3, c8 = (idx & 7) * 8;                                 \
            cp16(&(dst)[r * 72 + c8], &g_Vf[hb + (size_t)((j0) + r) * 64 + c8]);  \
        }                                                                         \
        cp_commit();                                                              \
    }

    // prologue: [Q + K(0)] group, V(0) group
#pragma unroll
    for (int i = 0; i < 4; i++) {
        int idx = i * 256 + tid;
        int r = idx >> 3, c8 = (idx & 7) * 8;
        cp16(&sQh[r * 72 + c8], &g_Qh[hb + (size_t)(i0 + r) * 64 + c8]);
        cp16(&sQl[r * 72 + c8], &g_Ql[hb + (size_t)(i0 + r) * 64 + c8]);
    }
    LOAD_K(0)          // group: Q + K(0)
    LOAD_V(0, sV0)     // group: V(0)
    cp_wait<1>();      // Q + K ready; V may still fly
    __syncthreads();

    float o[8][4];
#pragma unroll
    for (int d = 0; d < 8; d++)
#pragma unroll
        for (int k = 0; k < 4; k++) o[d][k] = 0.0f;
    float m0 = -1e30f, m1 = -1e30f, l0 = 0.0f, l1 = 0.0f;

    for (int jt = 0; jt < 8; jt++) {
        // ---- S = Q K^T ----
        float s[16][4];
#pragma unroll
        for (int t = 0; t < 16; t++)
#pragma unroll
            for (int k = 0; k < 4; k++) s[t][k] = 0.0f;

#pragma unroll
        for (int kt = 0; kt < 4; kt++) {
            uint32_t qh[4], ql[4];
            int qo = (warp * 16 + lr) * 72 + kt * 16 + lc;
            ldsm4(qh, &sQh[qo]);
            ldsm4(ql, &sQl[qo]);
#pragma unroll
            for (int nt = 0; nt < 8; nt++) {
                uint32_t kh[4], kl[4];
                int ko = (nt * 16 + lr) * 72 + kt * 16 + lc;
                ldsm4(kh, &sKh[ko]);
                ldsm4(kl, &sKl[ko]);
                float* s0 = s[nt * 2];
                float* s1 = s[nt * 2 + 1];
                mma_bf16(s0, qh, kh[0], kh[2]);
                mma_bf16(s1, qh, kh[1], kh[3]);
                mma_bf16(s0, qh, kl[0], kl[2]);
                mma_bf16(s1, qh, kl[1], kl[3]);
                mma_bf16(s0, ql, kh[0], kh[2]);
                mma_bf16(s1, ql, kh[1], kh[3]);
            }
        }

        // ---- online softmax (exp on MUFU, fp16x2; P stays packed) ----
        float rmax0 = -1e30f, rmax1 = -1e30f;
#pragma unroll
        for (int t = 0; t < 16; t++) {
            rmax0 = fmaxf(rmax0, fmaxf(s[t][0], s[t][1]));
            rmax1 = fmaxf(rmax1, fmaxf(s[t][2], s[t][3]));
        }
        rmax0 = fmaxf(rmax0, __shfl_xor_sync(0xffffffffu, rmax0, 1));
        rmax0 = fmaxf(rmax0, __shfl_xor_sync(0xffffffffu, rmax0, 2));
        rmax1 = fmaxf(rmax1, __shfl_xor_sync(0xffffffffu, rmax1, 1));
        rmax1 = fmaxf(rmax1, __shfl_xor_sync(0xffffffffu, rmax1, 2));
        float mn0 = fmaxf(m0, rmax0), mn1 = fmaxf(m1, rmax1);
        float cr0 = fast_exp(m0 - mn0), cr1 = fast_exp(m1 - mn1);
        float bb0 = mn0 * LOG2E, bb1 = mn1 * LOG2E;
        uint32_t p0[16], p1[16];
        float sum0 = 0.0f, sum1 = 0.0f;
#pragma unroll
        for (int t = 0; t < 16; t++) {
            float a0 = fmaf(s[t][0], LOG2E, -bb0);
            float a1 = fmaf(s[t][1], LOG2E, -bb0);
            float a2 = fmaf(s[t][2], LOG2E, -bb1);
            float a3 = fmaf(s[t][3], LOG2E, -bb1);
            __half2 h01 = __floats2half2_rn(a0, a1);
            __half2 h23 = __floats2half2_rn(a2, a3);
            uint32_t u01 = *reinterpret_cast<uint32_t*>(&h01);
            uint32_t u23 = *reinterpret_cast<uint32_t*>(&h23);
            asm("ex2.approx.f16x2 %0, %1;" : "=r"(p0[t]) : "r"(u01));
            asm("ex2.approx.f16x2 %0, %1;" : "=r"(p1[t]) : "r"(u23));
            __half2 e01 = *reinterpret_cast<__half2*>(&p0[t]);
            __half2 e23 = *reinterpret_cast<__half2*>(&p1[t]);
            float2 f01 = __half22float2(e01);
            float2 f23 = __half22float2(e23);
            sum0 += f01.x + f01.y;
            sum1 += f23.x + f23.y;
        }
        sum0 += __shfl_xor_sync(0xffffffffu, sum0, 1);
        sum0 += __shfl_xor_sync(0xffffffffu, sum0, 2);
        sum1 += __shfl_xor_sync(0xffffffffu, sum1, 1);
        sum1 += __shfl_xor_sync(0xffffffffu, sum1, 2);
        l0 = l0 * cr0 + sum0;
        l1 = l1 * cr1 + sum1;
        m0 = mn0;
        m1 = mn1;
#pragma unroll
        for (int d = 0; d < 8; d++) {
            o[d][0] *= cr0; o[d][1] *= cr0;
            o[d][2] *= cr1; o[d][3] *= cr1;
        }

        // ---- V(jt) landed; all K reads done; refill for jt+1 ----
        cp_wait<0>();
        __syncthreads();
        if (jt < 7) {
            const int jn = (jt + 1) * 128;
            LOAD_K(jn)                                   // group K(jt+1)
            LOAD_V(jn, ((jt + 1) & 1) ? sV1 : sV0)       // group V(jt+1)
        }

        // ---- O += P V (P already packed fp16x2 in p0/p1) ----
        __half* sV = (jt & 1) ? sV1 : sV0;
#pragma unroll
        for (int jt16 = 0; jt16 < 8; jt16++) {
            uint32_t a[4];
            a[0] = p0[jt16 * 2];
            a[1] = p1[jt16 * 2];
            a[2] = p0[jt16 * 2 + 1];
            a[3] = p1[jt16 * 2 + 1];
#pragma unroll
            for (int dt16 = 0; dt16 < 4; dt16++) {
                uint32_t v[4];
                ldsm4t(v, &sV[(jt16 * 16 + vrow) * 72 + dt16 * 16 + vcol]);
                mma_f16(o[dt16 * 2], a, v[0], v[1]);
                mma_f16(o[dt16 * 2 + 1], a, v[2], v[3]);
            }
        }

        if (jt < 7) {
            cp_wait<1>();     // K(jt+1) done; V(jt+1) may continue flying
            __syncthreads();
        }
    }
#undef LOAD_K
#undef LOAD_V

    // Epilogue: normalize, write fp16 g_Of [b*n][h*64+d]
    const float inv0 = 1.0f / l0, inv1 = 1.0f / l1;
    const int b_idx = bh >> 3, h = bh & 7;
    const size_t rowa = (size_t)b_idx * 1024 + i0 + warp * 16 + g;
    const size_t rowb = rowa + 8;
    const int colb = h * 64 + tig * 2;
#pragma unroll
    for (int dt = 0; dt < 8; dt++) {
        int col = colb + dt * 8;
        *(__half2*)&g_Of[rowa * 512 + col] =
            __floats2half2_rn(o[dt][0] * inv0, o[dt][1] * inv0);
        *(__half2*)&g_Of[rowb * 512 + col] =
            __floats2half2_rn(o[dt][2] * inv1, o[dt][3] * inv1);
    }
}

// ---------------------------------------------------------------------------
// Kernel 3: out = O @ w_out + b_out — round-11/15 proven fp16 2-stage verbatim.
__global__ __launch_bounds__(256, 2) void out_f16(const float* __restrict__ bias,
                                                  float* __restrict__ out) {
    extern __shared__ char sm[];
    const int STAGE = 2 * 128 * 72 * 2;   // 36864
    float c[4][4][4];
#pragma unroll
    for (int a = 0; a < 4; a++)
#pragma unroll
        for (int b = 0; b < 4; b++)
#pragma unroll
            for (int d = 0; d < 4; d++) c[a][b][d] = 0.0f;

    const int tid = threadIdx.x, lane = tid & 31, warp = tid >> 5;
    const int wy = warp >> 2, wx = warp & 3;
    const int lr = lane & 15, lc = (lane >> 4) * 8;
    const int row0 = blockIdx.y * 128, col0 = blockIdx.x * 128;

#define LOADF(kc, st)                                                             \
    {                                                                             \
        __half* dA = (__half*)(sm + (st) * STAGE);                                \
        __half* dB = dA + 128 * 72;                                               \
        _Pragma("unroll") for (int i = 0; i < 4; i++) {                           \
            int idx = i * 256 + tid;                                              \
            int r = idx >> 3, c8 = (idx & 7) * 8;                                 \
            cp16(&dA[r * 72 + c8], &g_Of[(size_t)(row0 + r) * 512 + (kc) + c8]);  \
            cp16(&dB[r * 72 + c8], &g_wof[(size_t)(col0 + r) * 512 + (kc) + c8]); \
        }                                                                         \
        cp_commit();                                                              \
    }

    LOADF(0, 0)
    for (int ks = 0; ks < 8; ks++) {
        if (ks < 7) {
            LOADF((ks + 1) * 64, (ks + 1) & 1)
            cp_wait<1>();
        } else {
            cp_wait<0>();
        }
        __syncthreads();
        __half* sA = (__half*)(sm + (ks & 1) * STAGE);
        __half* sB = sA + 128 * 72;
#pragma unroll
        for (int kt = 0; kt < 4; kt++) {
            uint32_t af[4][4];
#pragma unroll
            for (int mt = 0; mt < 4; mt++)
                ldsm4(af[mt], &sA[(wy * 64 + mt * 16 + lr) * 72 + kt * 16 + lc]);
#pragma unroll
            for (int nt16 = 0; nt16 < 2; nt16++) {
                uint32_t bf[4];
                ldsm4(bf, &sB[(wx * 32 + nt16 * 16 + lr) * 72 + kt * 16 + lc]);
#pragma unroll
                for (int mt = 0; mt < 4; mt++) {
                    mma_f16(c[mt][nt16 * 2], af[mt], bf[0], bf[2]);
                    mma_f16(c[mt][nt16 * 2 + 1], af[mt], bf[1], bf[3]);
                }
            }
        }
        __syncthreads();
    }
#undef LOADF

    const int g = lane >> 2, tig = lane & 3;
#pragma unroll
    for (int mt = 0; mt < 4; mt++)
#pragma unroll
        for (int nt = 0; nt < 4; nt++) {
            int r = row0 + wy * 64 + mt * 16 + g;
            int cc = col0 + wx * 32 + nt * 8 + tig * 2;
            float b0 = bias[cc], b1 = bias[cc + 1];
            *(float2*)&out[(size_t)r * 512 + cc] =
                make_float2(c[mt][nt][0] + b0, c[mt][nt][1] + b1);
            *(float2*)&out[(size_t)(r + 8) * 512 + cc] =
                make_float2(c[mt][nt][2] + b0, c[mt][nt][3] + b1);
        }
}

// ---------------------------------------------------------------------------
extern "C" void kernel_launch(void* const* d_in, const int* in_sizes, int n_in,
                              void* d_out, int out_size) {
    const float* x     = (const float*)d_in[0];
    const float* w_qkv = (const float*)d_in[1];
    const float* w_out = (const float*)d_in[2];
    const float* b_out = (const float*)d_in[3];
    float* out = (float*)d_out;

    const int gemm_smem = 4 * 128 * 72 * 2;     // 73728 B (covers Cs 67584)
    const int attn_smem = 6 * 128 * 72 * 2;     // 110592 B
    const int outf_smem = 2 * 2 * 128 * 72 * 2; // 73728 B
    cudaFuncSetAttribute(qkv_gemm_mma, cudaFuncAttributeMaxDynamicSharedMemorySize, gemm_smem);
    cudaFuncSetAttribute(attn_mma, cudaFuncAttributeMaxDynamicSharedMemorySize, attn_smem);
    cudaFuncSetAttribute(out_f16, cudaFuncAttributeMaxDynamicSharedMemorySize, outf_smem);

    prep_x<<<4096, 256>>>(x);
    prep_wq<<<dim3(48, 16), 256>>>(w_qkv);
    prep_wo<<<dim3(16, 16), 256>>>(w_out);
    qkv_gemm_mma<<<dim3(12, 64), 256, gemm_smem>>>();
    attn_mma<<<dim3(8, 64), 256, attn_smem>>>();
    out_f16<<<dim3(4, 64), 256, outf_smem>>>(b_out, out);
}